// round 2
// baseline (speedup 1.0000x reference)
#include <cuda_runtime.h>
#include <cstdint>

#define N_NODES 100000
#define N_EDGES 3200000

// ---------------------------------------------------------------------------
// Scratch (no allocations allowed -> __device__ globals)
// ---------------------------------------------------------------------------
__device__ float g_xr1[N_NODES * 32];   // x @ W1_rel^T
__device__ float g_acc1[N_NODES * 32];  // x @ W1_root^T + b1, then += scatter
__device__ float g_xr2[N_NODES * 32];
__device__ float g_acc2[N_NODES * 32];
__device__ float g_xr3[N_NODES * 8];
__device__ float g_wt1[128 * 64];       // k-major concat(W1_rel, W1_root)
__device__ float g_wt2[32 * 64];
__device__ float g_wt3[32 * 16];

// ---------------------------------------------------------------------------
// Transpose weights into k-major concatenated panels: wt[k][o],
// o in [0, HOUT) = rel rows, o in [HOUT, 2*HOUT) = root rows.
// ---------------------------------------------------------------------------
__global__ void transpose_weights_kernel(
    const float* __restrict__ w1r, const float* __restrict__ w1o,
    const float* __restrict__ w2r, const float* __restrict__ w2o,
    const float* __restrict__ w3r, const float* __restrict__ w3o)
{
    int tid = blockIdx.x * blockDim.x + threadIdx.x;
    int stride = gridDim.x * blockDim.x;
    // wt1: [128][64]
    for (int i = tid; i < 128 * 64; i += stride) {
        int k = i >> 6, o = i & 63;
        g_wt1[i] = (o < 32) ? w1r[o * 128 + k] : w1o[(o - 32) * 128 + k];
    }
    // wt2: [32][64]
    for (int i = tid; i < 32 * 64; i += stride) {
        int k = i >> 6, o = i & 63;
        g_wt2[i] = (o < 32) ? w2r[o * 32 + k] : w2o[(o - 32) * 32 + k];
    }
    // wt3: [32][16]
    for (int i = tid; i < 32 * 16; i += stride) {
        int k = i >> 4, o = i & 15;
        g_wt3[i] = (o < 8) ? w3r[o * 32 + k] : w3o[(o - 8) * 32 + k];
    }
}

// ---------------------------------------------------------------------------
// Fused node GEMM: computes BOTH
//   xr[n][0:HOUT]  = act(X[n]) @ W_rel^T
//   acc[n][0:HOUT] = act(X[n]) @ W_root^T + bias     (scatter target init)
// act = leaky_relu(0.01) applied on load when LRELU.
// Tiling: BM=64 nodes, BN=2*HOUT outputs, BK=32, 256 threads, 4xTN per thread.
// Weight panel Wt (k-major [K][BN]) fully resident in smem.
// ---------------------------------------------------------------------------
template<int K, int HOUT, bool LRELU>
__global__ __launch_bounds__(256)
void gemm_kernel(const float* __restrict__ X, const float* __restrict__ Wt,
                 const float* __restrict__ bias,
                 float* __restrict__ xr, float* __restrict__ acc)
{
    constexpr int BN = 2 * HOUT;        // 64 or 16
    constexpr int TN = BN / 16;         // 4 or 1
    constexpr int BM = 64;
    constexpr int BK = 32;

    __shared__ float As[BK][BM + 1];    // +1 pad: conflict-free transposed store
    __shared__ float Ws[K][BN];

    const int tid = threadIdx.x;
    const int tx = tid & 15;            // output-dim group
    const int ty = tid >> 4;            // node group
    const int m_blk = blockIdx.x * BM;

    // Load full k-major weight panel (coalesced float4)
    for (int i = tid * 4; i < K * BN; i += 256 * 4) {
        *(float4*)&Ws[0][i] = *(const float4*)&Wt[i];
    }

    float r[4][TN];
#pragma unroll
    for (int j = 0; j < 4; j++)
#pragma unroll
        for (int n = 0; n < TN; n++) r[j][n] = 0.f;

    for (int k0 = 0; k0 < K; k0 += BK) {
        __syncthreads();
        // Load A tile transposed: As[kk][m]
#pragma unroll
        for (int i = tid; i < BM * BK; i += 256) {
            int m = i >> 5, kk = i & 31;
            int node = m_blk + m;
            float v = 0.f;
            if (node < N_NODES) {
                v = X[(size_t)node * K + k0 + kk];
                if (LRELU) v = (v > 0.f) ? v : 0.01f * v;
            }
            As[kk][m] = v;
        }
        __syncthreads();

#pragma unroll
        for (int kk = 0; kk < BK; kk++) {
            float a[4];
#pragma unroll
            for (int j = 0; j < 4; j++) a[j] = As[kk][ty * 4 + j];
            float b[TN];
            if (TN == 4) {
                float4 bv = *(const float4*)&Ws[k0 + kk][tx * 4];
                b[0] = bv.x; b[1 % TN] = bv.y; b[2 % TN] = bv.z; b[3 % TN] = bv.w;
            } else {
                b[0] = Ws[k0 + kk][tx];
            }
#pragma unroll
            for (int j = 0; j < 4; j++)
#pragma unroll
                for (int n = 0; n < TN; n++)
                    r[j][n] += a[j] * b[n];
        }
    }

    // Epilogue: tx*TN in [0,HOUT) -> xr ; [HOUT,2*HOUT) -> acc (+bias)
#pragma unroll
    for (int j = 0; j < 4; j++) {
        int node = m_blk + ty * 4 + j;
        if (node >= N_NODES) continue;
        if (TN == 4) {
            if (tx < 8) {
                float4 v = make_float4(r[j][0], r[j][1 % TN], r[j][2 % TN], r[j][3 % TN]);
                *(float4*)&xr[(size_t)node * HOUT + tx * 4] = v;
            } else {
                int o = (tx - 8) * 4;
                float4 v = make_float4(r[j][0] + bias[o + 0],
                                       r[j][1 % TN] + bias[(o + 1) % HOUT],
                                       r[j][2 % TN] + bias[(o + 2) % HOUT],
                                       r[j][3 % TN] + bias[(o + 3) % HOUT]);
                *(float4*)&acc[(size_t)node * HOUT + o] = v;
            }
        } else {
            if (tx < HOUT) {
                xr[(size_t)node * HOUT + tx] = r[j][0];
            } else {
                int o = tx - HOUT;
                acc[(size_t)node * HOUT + o] = r[j][0] + bias[o];
            }
        }
    }
}

// ---------------------------------------------------------------------------
// Edge scatter: acc[dst] += ew * xr[src], D-dim rows, one float4 chunk per
// thread, vector L2 reduction (red.global.add.v4.f32, sm_90+).
// Edge arrays are streamed (.cs) -- read once, keep node tables in L2.
// ---------------------------------------------------------------------------
template<int D>
__global__ __launch_bounds__(256)
void scatter_kernel(const int* __restrict__ ei, const float* __restrict__ ew,
                    const float* __restrict__ xr, float* __restrict__ acc)
{
    constexpr int CPE = D / 4;                 // chunks per edge (8 or 2)
    const int total = N_EDGES * CPE;
    int gid = blockIdx.x * 256 + threadIdx.x;
    if (gid >= total) return;

    const int e = gid / CPE;
    const int c = gid - e * CPE;

    const int src = __ldcs(&ei[e]);
    const int dst = __ldcs(&ei[N_EDGES + e]);
    const float w = __ldcs(&ew[e]);

    float4 v = *(const float4*)(xr + (size_t)src * D + c * 4);
    v.x *= w; v.y *= w; v.z *= w; v.w *= w;

    float* p = acc + (size_t)dst * D + c * 4;
    asm volatile("red.global.add.v4.f32 [%0], {%1, %2, %3, %4};"
                 :: "l"(p), "f"(v.x), "f"(v.y), "f"(v.z), "f"(v.w)
                 : "memory");
}

// ---------------------------------------------------------------------------
// Launch
// ---------------------------------------------------------------------------
extern "C" void kernel_launch(void* const* d_in, const int* in_sizes, int n_in,
                              void* d_out, int out_size)
{
    const float* x      = (const float*)d_in[0];
    const int*   ei     = (const int*)d_in[1];
    const float* ew     = (const float*)d_in[2];
    const float* W1_rel = (const float*)d_in[3];
    const float* b1     = (const float*)d_in[4];
    const float* W1_root= (const float*)d_in[5];
    const float* W2_rel = (const float*)d_in[6];
    const float* b2     = (const float*)d_in[7];
    const float* W2_root= (const float*)d_in[8];
    const float* W3_rel = (const float*)d_in[9];
    const float* b3     = (const float*)d_in[10];
    const float* W3_root= (const float*)d_in[11];
    float* out = (float*)d_out;

    // Device-global scratch addresses (host side, capture-safe)
    float *xr1, *acc1, *xr2, *acc2, *xr3, *wt1, *wt2, *wt3;
    cudaGetSymbolAddress((void**)&xr1,  g_xr1);
    cudaGetSymbolAddress((void**)&acc1, g_acc1);
    cudaGetSymbolAddress((void**)&xr2,  g_xr2);
    cudaGetSymbolAddress((void**)&acc2, g_acc2);
    cudaGetSymbolAddress((void**)&xr3,  g_xr3);
    cudaGetSymbolAddress((void**)&wt1,  g_wt1);
    cudaGetSymbolAddress((void**)&wt2,  g_wt2);
    cudaGetSymbolAddress((void**)&wt3,  g_wt3);

    const int gemm_blocks = (N_NODES + 63) / 64;               // 1563
    const int sc32_blocks = (N_EDGES * 8 + 255) / 256;         // 100000
    const int sc8_blocks  = (N_EDGES * 2 + 255) / 256;         // 25000

    transpose_weights_kernel<<<16, 256>>>(W1_rel, W1_root, W2_rel, W2_root,
                                          W3_rel, W3_root);

    // Layer 1: project 128->32 first (commute W_rel with segment_sum)
    gemm_kernel<128, 32, false><<<gemm_blocks, 256>>>(x, wt1, b1, xr1, acc1);
    scatter_kernel<32><<<sc32_blocks, 256>>>(ei, ew, xr1, acc1);

    // Layer 2 (leaky-relu fused on load)
    gemm_kernel<32, 32, true><<<gemm_blocks, 256>>>(acc1, wt2, b2, xr2, acc2);
    scatter_kernel<32><<<sc32_blocks, 256>>>(ei, ew, xr2, acc2);

    // Layer 3 -> writes directly into d_out
    gemm_kernel<32, 8, true><<<gemm_blocks, 256>>>(acc2, wt3, b3, xr3, out);
    scatter_kernel<8><<<sc8_blocks, 256>>>(ei, ew, xr3, out);
}